// round 1
// baseline (speedup 1.0000x reference)
#include <cuda_runtime.h>
#include <math.h>

#define NN   50000
#define EE   800000
#define FIN  256
#define HID  256
#define FOUT 128

// ---------------- scratch (device globals; no allocation allowed) ----------
__device__ float g_bufA[NN * HID];    // xw of layer 1
__device__ float g_bufB[NN * HID];    // hidden after layer 1
__device__ float g_bufC[NN * FOUT];   // xw of layer 2 / residual
__device__ float g_dinv[NN];          // rsqrt(deg)
__device__ float g_deginv[NN];        // 1/deg
__device__ int   g_counts[NN];
__device__ int   g_cursor[NN];
__device__ int   g_rowptr[NN + 1];
__device__ int   g_col[EE];
__device__ float g_coef[EE];
__device__ int   g_fmt64;             // 1 if edges are int64, 0 if int32

// ---------------- edge dtype sniff -----------------------------------------
__global__ void k_detect(const int* e32) {
    __shared__ int nz;
    if (threadIdx.x == 0) nz = 0;
    __syncthreads();
    for (int i = threadIdx.x; i < 2048; i += blockDim.x) {
        // if data is int64 (values < 50000), every odd int32 word is 0
        if (e32[2 * i + 1] != 0) nz = 1;
    }
    __syncthreads();
    if (threadIdx.x == 0) g_fmt64 = (nz == 0) ? 1 : 0;
}

__device__ __forceinline__ int edge_at(const void* e, int idx) {
    if (g_fmt64) return (int)((const long long*)e)[idx];
    return ((const int*)e)[idx];
}

// ---------------- CSR build -------------------------------------------------
__global__ void k_zero_counts() {
    int i = blockIdx.x * blockDim.x + threadIdx.x;
    if (i < NN) g_counts[i] = 0;
}

__global__ void k_count(const void* edges) {
    int i = blockIdx.x * blockDim.x + threadIdx.x;
    if (i >= EE) return;
    int d = edge_at(edges, EE + i);
    atomicAdd(&g_counts[d], 1);
}

__global__ void k_deg() {
    int i = blockIdx.x * blockDim.x + threadIdx.x;
    if (i < NN) {
        float dg = (float)(g_counts[i] + 1);   // +1 self loop
        g_dinv[i]   = rsqrtf(dg);
        g_deginv[i] = 1.0f / dg;
    }
}

// single-block chunked inclusive scan -> exclusive rowptr
__global__ void k_scan() {
    __shared__ int sh[1024];
    __shared__ int carry;
    if (threadIdx.x == 0) { carry = 0; g_rowptr[0] = 0; }
    __syncthreads();
    for (int base = 0; base < NN; base += 1024) {
        int i = base + threadIdx.x;
        int v = (i < NN) ? g_counts[i] : 0;
        sh[threadIdx.x] = v;
        __syncthreads();
        for (int d = 1; d < 1024; d <<= 1) {
            int t = (threadIdx.x >= d) ? sh[threadIdx.x - d] : 0;
            __syncthreads();
            sh[threadIdx.x] += t;
            __syncthreads();
        }
        if (i < NN) {
            g_rowptr[i + 1] = carry + sh[threadIdx.x];
            g_cursor[i] = 0;
        }
        __syncthreads();
        if (threadIdx.x == 0) carry += sh[1023];
        __syncthreads();
    }
}

__global__ void k_fill(const void* edges) {
    int i = blockIdx.x * blockDim.x + threadIdx.x;
    if (i >= EE) return;
    int s = edge_at(edges, i);
    int d = edge_at(edges, EE + i);
    int pos = g_rowptr[d] + atomicAdd(&g_cursor[d], 1);
    g_col[pos]  = s;
    g_coef[pos] = g_dinv[s] * g_dinv[d];
}

// ---------------- SGEMM: C[M,Ncols] = A[M,K] @ W[K,Ncols] -------------------
// 64x64 tile, K-tile 16, 256 threads, 4x4 per thread
#define TM 64
#define TN 64
#define TK 16
__global__ void __launch_bounds__(256)
k_sgemm(const float* __restrict__ A, const float* __restrict__ W,
        float* __restrict__ C, int M, int K, int Ncols) {
    __shared__ float As[TK][TM + 4];
    __shared__ float Bs[TK][TN + 4];
    int bm = blockIdx.x * TM;
    int bn = blockIdx.y * TN;
    int tid = threadIdx.x;
    int tx = tid & 15;        // n tile coord
    int ty = tid >> 4;        // m tile coord
    float acc[4][4];
    #pragma unroll
    for (int i = 0; i < 4; i++)
        #pragma unroll
        for (int j = 0; j < 4; j++) acc[i][j] = 0.f;

    for (int k0 = 0; k0 < K; k0 += TK) {
        #pragma unroll
        for (int e = tid; e < TM * TK; e += 256) {
            int m = e >> 4, k = e & 15;
            int gm = bm + m;
            As[k][m] = (gm < M) ? A[(size_t)gm * K + k0 + k] : 0.f;
        }
        #pragma unroll
        for (int e = tid; e < TK * TN; e += 256) {
            int k = e >> 6, n = e & 63;
            Bs[k][n] = W[(size_t)(k0 + k) * Ncols + bn + n];
        }
        __syncthreads();
        #pragma unroll
        for (int k = 0; k < TK; k++) {
            float a[4], b[4];
            #pragma unroll
            for (int i = 0; i < 4; i++) a[i] = As[k][ty * 4 + i];
            #pragma unroll
            for (int j = 0; j < 4; j++) b[j] = Bs[k][tx * 4 + j];
            #pragma unroll
            for (int i = 0; i < 4; i++)
                #pragma unroll
                for (int j = 0; j < 4; j++) acc[i][j] += a[i] * b[j];
        }
        __syncthreads();
    }
    #pragma unroll
    for (int i = 0; i < 4; i++) {
        int gm = bm + ty * 4 + i;
        if (gm >= M) continue;
        #pragma unroll
        for (int j = 0; j < 4; j++)
            C[(size_t)gm * Ncols + bn + tx * 4 + j] = acc[i][j];
    }
}

// ---------------- GCN aggregation + self loop + bias + LeakyReLU ------------
template <int F>
__global__ void k_agg(const float* __restrict__ xw, const float* __restrict__ bias,
                      float* __restrict__ out) {
    int row = blockIdx.x;
    int f = threadIdx.x;
    int start = g_rowptr[row];
    int end   = g_rowptr[row + 1];
    float acc = 0.f;
    for (int p = start; p < end; p++) {
        int s   = g_col[p];
        float c = g_coef[p];
        acc += xw[(size_t)s * F + f] * c;
    }
    float v = acc + xw[(size_t)row * F + f] * g_deginv[row] + bias[f];
    out[(size_t)row * F + f] = (v >= 0.f) ? v : 0.2f * v;
}

// ---------------- final combine --------------------------------------------
__global__ void k_combine(const float* __restrict__ jv, const float* __restrict__ bv,
                          const float* __restrict__ res, const float* __restrict__ bias,
                          float* __restrict__ out) {
    int i = blockIdx.x * blockDim.x + threadIdx.x;
    if (i < NN * FOUT) {
        out[i] = 0.5f * (jv[i] + bv[i]) + res[i] + bias[i & (FOUT - 1)];
    }
}

// ---------------- host orchestration ----------------------------------------
static void run_view(const float* x, const void* edges,
                     const float* W1, const float* b1,
                     const float* W2, const float* b2,
                     float* out_view,
                     float* bufA, float* bufB, float* bufC) {
    k_zero_counts<<<(NN + 255) / 256, 256>>>();
    k_count<<<(EE + 255) / 256, 256>>>(edges);
    k_deg<<<(NN + 255) / 256, 256>>>();
    k_scan<<<1, 1024>>>();
    k_fill<<<(EE + 255) / 256, 256>>>(edges);

    dim3 g1((NN + TM - 1) / TM, HID / TN);
    k_sgemm<<<g1, 256>>>(x, W1, bufA, NN, FIN, HID);
    k_agg<HID><<<NN, HID>>>(bufA, b1, bufB);

    dim3 g2((NN + TM - 1) / TM, FOUT / TN);
    k_sgemm<<<g2, 256>>>(bufB, W2, bufC, NN, HID, FOUT);
    k_agg<FOUT><<<NN, FOUT>>>(bufC, b2, out_view);
}

extern "C" void kernel_launch(void* const* d_in, const int* in_sizes, int n_in,
                              void* d_out, int out_size) {
    const float* x_lj = (const float*)d_in[0];
    const float* x_pj = (const float*)d_in[1];
    const float* x_lb = (const float*)d_in[2];
    const float* x_pb = (const float*)d_in[3];
    const void*  e_jl = d_in[4];
    const void*  e_jp = d_in[5];
    const void*  e_bl = d_in[6];
    const void*  e_bp = d_in[7];

    const float* W_j1_l = (const float*)d_in[8];   const float* b_j1_l = (const float*)d_in[9];
    const float* W_j1_p = (const float*)d_in[10];  const float* b_j1_p = (const float*)d_in[11];
    const float* W_j2_l = (const float*)d_in[12];  const float* b_j2_l = (const float*)d_in[13];
    const float* W_j2_p = (const float*)d_in[14];  const float* b_j2_p = (const float*)d_in[15];
    const float* W_b1_l = (const float*)d_in[16];  const float* b_b1_l = (const float*)d_in[17];
    const float* W_b1_p = (const float*)d_in[18];  const float* b_b1_p = (const float*)d_in[19];
    const float* W_b2_l = (const float*)d_in[20];  const float* b_b2_l = (const float*)d_in[21];
    const float* W_b2_p = (const float*)d_in[22];  const float* b_b2_p = (const float*)d_in[23];
    const float* W_r_l  = (const float*)d_in[24];  const float* b_r_l  = (const float*)d_in[25];
    const float* W_r_p  = (const float*)d_in[26];  const float* b_r_p  = (const float*)d_in[27];

    float* out = (float*)d_out;
    const size_t SEC = (size_t)NN * FOUT;
    float* comb_l = out + 0 * SEC;
    float* comb_p = out + 1 * SEC;
    float* jl     = out + 2 * SEC;
    float* jp     = out + 3 * SEC;
    float* bl     = out + 4 * SEC;
    float* bp     = out + 5 * SEC;

    float *bufA, *bufB, *bufC;
    cudaGetSymbolAddress((void**)&bufA, g_bufA);
    cudaGetSymbolAddress((void**)&bufB, g_bufB);
    cudaGetSymbolAddress((void**)&bufC, g_bufC);

    // detect edge dtype (int64 vs int32) once; all 4 edge arrays share it
    k_detect<<<1, 256>>>((const int*)e_jl);

    run_view(x_lj, e_jl, W_j1_l, b_j1_l, W_j2_l, b_j2_l, jl, bufA, bufB, bufC);
    run_view(x_pj, e_jp, W_j1_p, b_j1_p, W_j2_p, b_j2_p, jp, bufA, bufB, bufC);
    run_view(x_lb, e_bl, W_b1_l, b_b1_l, W_b2_l, b_b2_l, bl, bufA, bufB, bufC);
    run_view(x_pb, e_bp, W_b1_p, b_b1_p, W_b2_p, b_b2_p, bp, bufA, bufB, bufC);

    // residual GEMMs + combines
    dim3 gr((NN + TM - 1) / TM, FOUT / TN);
    int cb = (NN * FOUT + 255) / 256;
    k_sgemm<<<gr, 256>>>(x_lj, W_r_l, bufC, NN, FIN, FOUT);
    k_combine<<<cb, 256>>>(jl, bl, bufC, b_r_l, comb_l);
    k_sgemm<<<gr, 256>>>(x_pj, W_r_p, bufC, NN, FIN, FOUT);
    k_combine<<<cb, 256>>>(jp, bp, bufC, b_r_p, comb_p);
}

// round 5
// speedup vs baseline: 1.4151x; 1.4151x over previous
#include <cuda_runtime.h>
#include <cstdint>
#include <math.h>

#define NN   50000
#define EE   800000
#define FIN  256
#define HID  256
#define FOUT 128

// ---------------- scratch (device globals; no allocation allowed) ----------
__device__ float g_bufA[NN * HID];    // xw of layer 1
__device__ float g_bufB[NN * HID];    // hidden after layer 1
__device__ float g_bufC[NN * FOUT];   // xw of layer 2 / residual
__device__ float g_wt[256 * 256];     // transposed weight scratch
__device__ float g_dinv[NN];          // rsqrt(deg)
__device__ float g_deginv[NN];        // 1/deg
__device__ int   g_counts[NN];
__device__ int   g_cursor[NN];
__device__ int   g_rowptr[NN + 1];
__device__ int   g_col[EE];
__device__ float g_coef[EE];
__device__ int   g_fmt64;             // 1 if edges are int64, 0 if int32

// ==================== mma.sync 3xTF32 GEMM (baseline PTX, sm_80+) ===========
// C[M, NC] = A[M, 256] @ Bt^T, Bt is [NC, 256] K-major (pre-transposed W).
// CTA tile 128x128, BK=32, 8 warps (4M x 2N), warp tile 32x64,
// mma.m16n8k8.row.col tf32 with hi/lo split (3 MMAs) for ~fp32 accuracy,
// cp.async double buffering.

__device__ __forceinline__ void cp16(uint32_t dst, const void* src, int nbytes) {
    asm volatile("cp.async.cg.shared.global [%0], [%1], 16, %2;"
                 :: "r"(dst), "l"(src), "r"(nbytes));
}

__device__ __forceinline__ void mma_tf32(float* d, const uint32_t* a, const uint32_t* b) {
    asm volatile(
        "mma.sync.aligned.m16n8k8.row.col.f32.tf32.tf32.f32 "
        "{%0,%1,%2,%3}, {%4,%5,%6,%7}, {%8,%9}, {%0,%1,%2,%3};"
        : "+f"(d[0]), "+f"(d[1]), "+f"(d[2]), "+f"(d[3])
        : "r"(a[0]), "r"(a[1]), "r"(a[2]), "r"(a[3]), "r"(b[0]), "r"(b[1]));
}

__device__ __forceinline__ float to_tf32(float x) {
    float r;
    asm("cvt.rna.tf32.f32 %0, %1;" : "=f"(r) : "f"(x));
    return r;
}

__device__ __forceinline__ uint32_t smem_u32(const void* p) {
    uint32_t a;
    asm("{ .reg .u64 t; cvta.to.shared.u64 t, %1; cvt.u32.u64 %0, t; }"
        : "=r"(a) : "l"(p));
    return a;
}

#define LDSA 36                     // padded smem stride in floats
#define BUF_FLOATS (128 * LDSA)     // 4608 floats = 18432 B per buffer
#define SMEM_GEMM (4 * BUF_FLOATS * 4)  // As0,As1,Bs0,Bs1 = 73728 B

template<int NC>
__global__ void __launch_bounds__(256, 1)
k_gemm_mma(const float* __restrict__ A, const float* __restrict__ Bt,
           float* __restrict__ C, int M)
{
    extern __shared__ float sm[];
    float* As = sm;                       // [2][BUF_FLOATS]
    float* Bs = sm + 2 * BUF_FLOATS;      // [2][BUF_FLOATS]
    const uint32_t sA = smem_u32(As);
    const uint32_t sB = smem_u32(Bs);

    const int tid  = threadIdx.x;
    const int warp = tid >> 5, lane = tid & 31;
    const int wm = (warp & 3) * 32;       // warp M offset in tile
    const int wn = (warp >> 2) * 64;      // warp N offset in tile
    const int r  = lane >> 2, c = lane & 3;
    const int bm  = blockIdx.x * 128;
    const int bn0 = blockIdx.y * 128;

    // per-thread load coords: 4 float4 each for A and B per ktile
    const int lr0 = tid >> 3;             // base row (0..31), +i*32
    const int lc4 = tid & 7;              // float4 col within 32-wide chunk

    float acc[2][8][4];
    #pragma unroll
    for (int t = 0; t < 2; t++)
        #pragma unroll
        for (int u = 0; u < 8; u++)
            #pragma unroll
            for (int i = 0; i < 4; i++) acc[t][u][i] = 0.f;

    // ---- tile loader ----
    auto load_tile = [&](int kt, int buf) {
        const int k0 = kt * 32;
        #pragma unroll
        for (int i = 0; i < 4; i++) {
            const int row = lr0 + i * 32;
            const uint32_t soff = (uint32_t)((row * LDSA + lc4 * 4) * 4);
            // A (row-guarded, zero-fill OOB)
            const int grow = bm + row;
            const int rowok = (grow < M) ? grow : 0;
            cp16(sA + buf * (BUF_FLOATS * 4) + soff,
                 A + (size_t)rowok * 256 + k0 + lc4 * 4,
                 (grow < M) ? 16 : 0);
            // B (always in bounds: NC rows)
            cp16(sB + buf * (BUF_FLOATS * 4) + soff,
                 Bt + (size_t)(bn0 + row) * 256 + k0 + lc4 * 4, 16);
        }
    };

    load_tile(0, 0);
    asm volatile("cp.async.commit_group;" ::: "memory");
    load_tile(1, 1);
    asm volatile("cp.async.commit_group;" ::: "memory");

    #pragma unroll 1
    for (int kt = 0; kt < 8; kt++) {
        asm volatile("cp.async.wait_group 1;" ::: "memory");
        __syncthreads();

        const int buf = kt & 1;
        const float* Ab = As + buf * BUF_FLOATS;
        const float* Bb = Bs + buf * BUF_FLOATS;
        #pragma unroll
        for (int ks = 0; ks < 4; ks++) {
            const int kk = ks * 8;
            uint32_t afh[2][4], afl[2][4], bfh[8][2], bfl[8][2];
            #pragma unroll
            for (int t = 0; t < 2; t++) {
                const float* ap = Ab + (wm + t * 16 + r) * LDSA + kk + c;
                float v0 = ap[0], v1 = ap[8 * LDSA], v2 = ap[4], v3 = ap[8 * LDSA + 4];
                float h0 = to_tf32(v0), h1 = to_tf32(v1), h2 = to_tf32(v2), h3 = to_tf32(v3);
                afh[t][0] = __float_as_uint(h0);
                afh[t][1] = __float_as_uint(h1);
                afh[t][2] = __float_as_uint(h2);
                afh[t][3] = __float_as_uint(h3);
                afl[t][0] = __float_as_uint(to_tf32(v0 - h0));
                afl[t][1] = __float_as_uint(to_tf32(v1 - h1));
                afl[t][2] = __float_as_uint(to_tf32(v2 - h2));
                afl[t][3] = __float_as_uint(to_tf32(v3 - h3));
            }
            #pragma unroll
            for (int u = 0; u < 8; u++) {
                const float* bp = Bb + (wn + u * 8 + r) * LDSA + kk + c;
                float v0 = bp[0], v1 = bp[4];
                float h0 = to_tf32(v0), h1 = to_tf32(v1);
                bfh[u][0] = __float_as_uint(h0);
                bfh[u][1] = __float_as_uint(h1);
                bfl[u][0] = __float_as_uint(to_tf32(v0 - h0));
                bfl[u][1] = __float_as_uint(to_tf32(v1 - h1));
            }
            #pragma unroll
            for (int t = 0; t < 2; t++)
                #pragma unroll
                for (int u = 0; u < 8; u++) {
                    mma_tf32(acc[t][u], afl[t], bfh[u]);   // lo*hi
                    mma_tf32(acc[t][u], afh[t], bfl[u]);   // hi*lo
                    mma_tf32(acc[t][u], afh[t], bfh[u]);   // hi*hi last (largest)
                }
        }
        __syncthreads();
        if (kt + 2 < 8) load_tile(kt + 2, buf);
        asm volatile("cp.async.commit_group;" ::: "memory");
    }

    // ---- epilogue ----
    #pragma unroll
    for (int t = 0; t < 2; t++) {
        const int row0 = bm + wm + t * 16 + r;
        #pragma unroll
        for (int u = 0; u < 8; u++) {
            const int col = bn0 + wn + u * 8 + 2 * c;
            if (row0 < M)
                *(float2*)(C + (size_t)row0 * NC + col) =
                    make_float2(acc[t][u][0], acc[t][u][1]);
            if (row0 + 8 < M)
                *(float2*)(C + (size_t)(row0 + 8) * NC + col) =
                    make_float2(acc[t][u][2], acc[t][u][3]);
        }
    }
}

// ---------------- weight transpose: W[K,Ncols] -> Wt[Ncols,K] ----------------
__global__ void k_transpose(const float* __restrict__ W, float* __restrict__ Wt,
                            int K, int Ncols) {
    int i = blockIdx.x * blockDim.x + threadIdx.x;
    if (i < K * Ncols) {
        int k = i / Ncols, n = i % Ncols;
        Wt[n * K + k] = W[i];
    }
}

// ---------------- edge dtype sniff -----------------------------------------
__global__ void k_detect(const int* e32) {
    __shared__ int nz;
    if (threadIdx.x == 0) nz = 0;
    __syncthreads();
    for (int i = threadIdx.x; i < 2048; i += blockDim.x) {
        if (e32[2 * i + 1] != 0) nz = 1;
    }
    __syncthreads();
    if (threadIdx.x == 0) g_fmt64 = (nz == 0) ? 1 : 0;
}

__device__ __forceinline__ int edge_at(const void* e, int idx) {
    if (g_fmt64) return (int)((const long long*)e)[idx];
    return ((const int*)e)[idx];
}

// ---------------- CSR build -------------------------------------------------
__global__ void k_zero_counts() {
    int i = blockIdx.x * blockDim.x + threadIdx.x;
    if (i < NN) g_counts[i] = 0;
}

__global__ void k_count(const void* edges) {
    int i = blockIdx.x * blockDim.x + threadIdx.x;
    if (i >= EE) return;
    int d = edge_at(edges, EE + i);
    atomicAdd(&g_counts[d], 1);
}

__global__ void k_deg() {
    int i = blockIdx.x * blockDim.x + threadIdx.x;
    if (i < NN) {
        float dg = (float)(g_counts[i] + 1);   // +1 self loop
        g_dinv[i]   = rsqrtf(dg);
        g_deginv[i] = 1.0f / dg;
    }
}

__global__ void k_scan() {
    __shared__ int sh[1024];
    __shared__ int carry;
    if (threadIdx.x == 0) { carry = 0; g_rowptr[0] = 0; }
    __syncthreads();
    for (int base = 0; base < NN; base += 1024) {
        int i = base + threadIdx.x;
        int v = (i < NN) ? g_counts[i] : 0;
        sh[threadIdx.x] = v;
        __syncthreads();
        for (int d = 1; d < 1024; d <<= 1) {
            int t = (threadIdx.x >= d) ? sh[threadIdx.x - d] : 0;
            __syncthreads();
            sh[threadIdx.x] += t;
            __syncthreads();
        }
        if (i < NN) {
            g_rowptr[i + 1] = carry + sh[threadIdx.x];
            g_cursor[i] = 0;
        }
        __syncthreads();
        if (threadIdx.x == 0) carry += sh[1023];
        __syncthreads();
    }
}

__global__ void k_fill(const void* edges) {
    int i = blockIdx.x * blockDim.x + threadIdx.x;
    if (i >= EE) return;
    int s = edge_at(edges, i);
    int d = edge_at(edges, EE + i);
    int pos = g_rowptr[d] + atomicAdd(&g_cursor[d], 1);
    g_col[pos]  = s;
    g_coef[pos] = g_dinv[s] * g_dinv[d];
}

// ---------------- GCN aggregation + self loop + bias + LeakyReLU ------------
// float4-vectorized: 256 threads, F/4 threads per row
template <int F>
__global__ void __launch_bounds__(256)
k_agg(const float* __restrict__ xw, const float* __restrict__ bias,
      float* __restrict__ out) {
    constexpr int TPR = F / 4;        // threads per row
    constexpr int RPB = 256 / TPR;    // rows per block
    const int rid = threadIdx.x / TPR;
    const int f4  = threadIdx.x % TPR;
    const int row = blockIdx.x * RPB + rid;
    if (row >= NN) return;

    const int start = g_rowptr[row];
    const int end   = g_rowptr[row + 1];
    float4 acc = make_float4(0.f, 0.f, 0.f, 0.f);
    for (int p = start; p < end; p++) {
        const int s    = g_col[p];
        const float cf = g_coef[p];
        float4 v = *(const float4*)(xw + (size_t)s * F + f4 * 4);
        acc.x += v.x * cf; acc.y += v.y * cf;
        acc.z += v.z * cf; acc.w += v.w * cf;
    }
    const float di = g_deginv[row];
    float4 sv = *(const float4*)(xw + (size_t)row * F + f4 * 4);
    float4 bv = *(const float4*)(bias + f4 * 4);
    float4 o;
    o.x = acc.x + sv.x * di + bv.x;
    o.y = acc.y + sv.y * di + bv.y;
    o.z = acc.z + sv.z * di + bv.z;
    o.w = acc.w + sv.w * di + bv.w;
    o.x = (o.x >= 0.f) ? o.x : 0.2f * o.x;
    o.y = (o.y >= 0.f) ? o.y : 0.2f * o.y;
    o.z = (o.z >= 0.f) ? o.z : 0.2f * o.z;
    o.w = (o.w >= 0.f) ? o.w : 0.2f * o.w;
    *(float4*)(out + (size_t)row * F + f4 * 4) = o;
}

// ---------------- final combine --------------------------------------------
__global__ void k_combine(const float* __restrict__ jv, const float* __restrict__ bv,
                          const float* __restrict__ res, const float* __restrict__ bias,
                          float* __restrict__ out) {
    int i = blockIdx.x * blockDim.x + threadIdx.x;
    if (i < NN * FOUT) {
        out[i] = 0.5f * (jv[i] + bv[i]) + res[i] + bias[i & (FOUT - 1)];
    }
}

// ---------------- host orchestration ----------------------------------------
#define GEMM_GRID_X ((NN + 127) / 128)

static void run_view(const float* x, const void* edges,
                     const float* W1, const float* b1,
                     const float* W2, const float* b2,
                     float* out_view,
                     float* bufA, float* bufB, float* bufC, float* wt) {
    k_zero_counts<<<(NN + 255) / 256, 256>>>();
    k_count<<<(EE + 255) / 256, 256>>>(edges);
    k_deg<<<(NN + 255) / 256, 256>>>();
    k_scan<<<1, 1024>>>();
    k_fill<<<(EE + 255) / 256, 256>>>(edges);

    // layer 1: NC = HID = 256
    k_transpose<<<(FIN * HID + 255) / 256, 256>>>(W1, wt, FIN, HID);
    k_gemm_mma<256><<<dim3(GEMM_GRID_X, 2), 256, SMEM_GEMM>>>(x, wt, bufA, NN);
    k_agg<HID><<<(NN + 3) / 4, 256>>>(bufA, b1, bufB);

    // layer 2: NC = FOUT = 128
    k_transpose<<<(HID * FOUT + 255) / 256, 256>>>(W2, wt, HID, FOUT);
    k_gemm_mma<128><<<dim3(GEMM_GRID_X, 1), 256, SMEM_GEMM>>>(bufB, wt, bufC, NN);
    k_agg<FOUT><<<(NN + 7) / 8, 256>>>(bufC, b2, out_view);
}

extern "C" void kernel_launch(void* const* d_in, const int* in_sizes, int n_in,
                              void* d_out, int out_size) {
    const float* x_lj = (const float*)d_in[0];
    const float* x_pj = (const float*)d_in[1];
    const float* x_lb = (const float*)d_in[2];
    const float* x_pb = (const float*)d_in[3];
    const void*  e_jl = d_in[4];
    const void*  e_jp = d_in[5];
    const void*  e_bl = d_in[6];
    const void*  e_bp = d_in[7];

    const float* W_j1_l = (const float*)d_in[8];   const float* b_j1_l = (const float*)d_in[9];
    const float* W_j1_p = (const float*)d_in[10];  const float* b_j1_p = (const float*)d_in[11];
    const float* W_j2_l = (const float*)d_in[12];  const float* b_j2_l = (const float*)d_in[13];
    const float* W_j2_p = (const float*)d_in[14];  const float* b_j2_p = (const float*)d_in[15];
    const float* W_b1_l = (const float*)d_in[16];  const float* b_b1_l = (const float*)d_in[17];
    const float* W_b1_p = (const float*)d_in[18];  const float* b_b1_p = (const float*)d_in[19];
    const float* W_b2_l = (const float*)d_in[20];  const float* b_b2_l = (const float*)d_in[21];
    const float* W_b2_p = (const float*)d_in[22];  const float* b_b2_p = (const float*)d_in[23];
    const float* W_r_l  = (const float*)d_in[24];  const float* b_r_l  = (const float*)d_in[25];
    const float* W_r_p  = (const float*)d_in[26];  const float* b_r_p  = (const float*)d_in[27];

    float* out = (float*)d_out;
    const size_t SEC = (size_t)NN * FOUT;
    float* comb_l = out + 0 * SEC;
    float* comb_p = out + 1 * SEC;
    float* jl     = out + 2 * SEC;
    float* jp     = out + 3 * SEC;
    float* bl     = out + 4 * SEC;
    float* bp     = out + 5 * SEC;

    float *bufA, *bufB, *bufC, *wt;
    cudaGetSymbolAddress((void**)&bufA, g_bufA);
    cudaGetSymbolAddress((void**)&bufB, g_bufB);
    cudaGetSymbolAddress((void**)&bufC, g_bufC);
    cudaGetSymbolAddress((void**)&wt,   g_wt);

    cudaFuncSetAttribute(k_gemm_mma<256>, cudaFuncAttributeMaxDynamicSharedMemorySize, SMEM_GEMM);
    cudaFuncSetAttribute(k_gemm_mma<128>, cudaFuncAttributeMaxDynamicSharedMemorySize, SMEM_GEMM);

    // detect edge dtype (int64 vs int32) once; all 4 edge arrays share it
    k_detect<<<1, 256>>>((const int*)e_jl);

    run_view(x_lj, e_jl, W_j1_l, b_j1_l, W_j2_l, b_j2_l, jl, bufA, bufB, bufC, wt);
    run_view(x_pj, e_jp, W_j1_p, b_j1_p, W_j2_p, b_j2_p, jp, bufA, bufB, bufC, wt);
    run_view(x_lb, e_bl, W_b1_l, b_b1_l, W_b2_l, b_b2_l, bl, bufA, bufB, bufC, wt);
    run_view(x_pb, e_bp, W_b1_p, b_b1_p, W_b2_p, b_b2_p, bp, bufA, bufB, bufC, wt);

    // residual GEMMs + combines (NC = 128)
    int cb = (NN * FOUT + 255) / 256;
    k_transpose<<<(FIN * FOUT + 255) / 256, 256>>>(W_r_l, wt, FIN, FOUT);
    k_gemm_mma<128><<<dim3(GEMM_GRID_X, 1), 256, SMEM_GEMM>>>(x_lj, wt, bufC, NN);
    k_combine<<<cb, 256>>>(jl, bl, bufC, b_r_l, comb_l);
    k_transpose<<<(FIN * FOUT + 255) / 256, 256>>>(W_r_p, wt, FIN, FOUT);
    k_gemm_mma<128><<<dim3(GEMM_GRID_X, 1), 256, SMEM_GEMM>>>(x_pj, wt, bufC, NN);
    k_combine<<<cb, 256>>>(jp, bp, bufC, b_r_p, comb_p);
}

// round 6
// speedup vs baseline: 2.1625x; 1.5282x over previous
#include <cuda_runtime.h>
#include <cstdint>
#include <math.h>

#define NN   50000
#define EE   800000
#define FIN  256
#define HID  256
#define FOUT 128

// ---------------- scratch (device globals; no allocation allowed) ----------
__device__ float g_bufA[4][NN * HID];   // xw of layer 1, per view
__device__ float g_bufB[4][NN * HID];   // hidden after layer 1, per view
__device__ float g_bufC[4][NN * FOUT];  // xw of layer 2 / residual, per view
__device__ float g_wts[4 * 65536 + 6 * 32768];  // all transposed weights
__device__ float g_dinv[4][NN];
__device__ float g_deginv[4][NN];
__device__ int   g_counts[4][NN];
__device__ int   g_cursor[4][NN];
__device__ int   g_rowptr[4][NN + 1];
__device__ int   g_col[4][EE];
__device__ float g_coef[4][EE];
__device__ int   g_fmt64;

struct Ptr4 { const float* p[4]; };

// ==================== mma.sync 3xBF16 GEMM (baseline PTX, sm_80+) ===========
// C[M, NC] = A[M, 256] @ Bt^T, Bt is [NC, 256] K-major (pre-transposed W).
// CTA tile 128x128, BK=32, 8 warps (4M x 2N), warp tile 32x64,
// mma.m16n8k16.row.col bf16 with hi/lo split (3 MMAs) ~1e-5 accuracy,
// cp.async double buffering.

__device__ __forceinline__ void cp16(uint32_t dst, const void* src, int nbytes) {
    asm volatile("cp.async.cg.shared.global [%0], [%1], 16, %2;"
                 :: "r"(dst), "l"(src), "r"(nbytes));
}

__device__ __forceinline__ void mma_bf16(float* d, const uint32_t* a, const uint32_t* b) {
    asm volatile(
        "mma.sync.aligned.m16n8k16.row.col.f32.bf16.bf16.f32 "
        "{%0,%1,%2,%3}, {%4,%5,%6,%7}, {%8,%9}, {%0,%1,%2,%3};"
        : "+f"(d[0]), "+f"(d[1]), "+f"(d[2]), "+f"(d[3])
        : "r"(a[0]), "r"(a[1]), "r"(a[2]), "r"(a[3]), "r"(b[0]), "r"(b[1]));
}

// pack {lo_elem=x, hi_elem=y} into bf16x2
__device__ __forceinline__ uint32_t pack_bf16(float x, float y) {
    uint32_t r;
    asm("cvt.rn.bf16x2.f32 %0, %1, %2;" : "=r"(r) : "f"(y), "f"(x));
    return r;
}

// split float2 into bf16x2 hi + bf16x2 lo (residual)
__device__ __forceinline__ void split2(float2 v, uint32_t& hi, uint32_t& lo) {
    hi = pack_bf16(v.x, v.y);
    float h0 = __uint_as_float(hi << 16);
    float h1 = __uint_as_float(hi & 0xffff0000u);
    lo = pack_bf16(v.x - h0, v.y - h1);
}

__device__ __forceinline__ uint32_t smem_u32(const void* p) {
    uint32_t a;
    asm("{ .reg .u64 t; cvta.to.shared.u64 t, %1; cvt.u32.u64 %0, t; }"
        : "=r"(a) : "l"(p));
    return a;
}

#define LDSA 40                     // padded stride: conflict-free LDS.64 frags
#define BUF_FLOATS (128 * LDSA)     // 5120 floats = 20480 B per buffer
#define SMEM_GEMM (4 * BUF_FLOATS * 4)  // As0,As1,Bs0,Bs1 = 81920 B

template<int NC>
__global__ void __launch_bounds__(256, 1)
k_gemm(Ptr4 Av, const float* __restrict__ WtBase, int wtStride,
       float* __restrict__ Cbase, size_t cStride, int M)
{
    const int view = blockIdx.z;
    const float* __restrict__ A  = Av.p[view];
    const float* __restrict__ Bt = WtBase + (size_t)view * wtStride;
    float* __restrict__ C        = Cbase + (size_t)view * cStride;

    extern __shared__ float sm[];
    float* As = sm;                       // [2][BUF_FLOATS]
    float* Bs = sm + 2 * BUF_FLOATS;      // [2][BUF_FLOATS]
    const uint32_t sA = smem_u32(As);
    const uint32_t sB = smem_u32(Bs);

    const int tid  = threadIdx.x;
    const int warp = tid >> 5, lane = tid & 31;
    const int wm = (warp & 3) * 32;       // warp M offset in tile
    const int wn = (warp >> 2) * 64;      // warp N offset in tile
    const int r  = lane >> 2, c = lane & 3;
    const int bm  = blockIdx.x * 128;
    const int bn0 = blockIdx.y * 128;

    const int lr0 = tid >> 3;             // loader base row (0..31), +i*32
    const int lc4 = tid & 7;              // loader float4 col

    float acc[2][8][4];
    #pragma unroll
    for (int t = 0; t < 2; t++)
        #pragma unroll
        for (int u = 0; u < 8; u++)
            #pragma unroll
            for (int i = 0; i < 4; i++) acc[t][u][i] = 0.f;

    auto load_tile = [&](int kt, int buf) {
        const int k0 = kt * 32;
        #pragma unroll
        for (int i = 0; i < 4; i++) {
            const int row = lr0 + i * 32;
            const uint32_t soff = (uint32_t)((row * LDSA + lc4 * 4) * 4);
            const int grow = bm + row;
            const int rowok = (grow < M) ? grow : 0;
            cp16(sA + buf * (BUF_FLOATS * 4) + soff,
                 A + (size_t)rowok * 256 + k0 + lc4 * 4,
                 (grow < M) ? 16 : 0);
            cp16(sB + buf * (BUF_FLOATS * 4) + soff,
                 Bt + (size_t)(bn0 + row) * 256 + k0 + lc4 * 4, 16);
        }
    };

    load_tile(0, 0);
    asm volatile("cp.async.commit_group;" ::: "memory");
    load_tile(1, 1);
    asm volatile("cp.async.commit_group;" ::: "memory");

    #pragma unroll 1
    for (int kt = 0; kt < 8; kt++) {
        asm volatile("cp.async.wait_group 1;" ::: "memory");
        __syncthreads();

        const int buf = kt & 1;
        const float* Ab = As + buf * BUF_FLOATS;
        const float* Bb = Bs + buf * BUF_FLOATS;
        #pragma unroll
        for (int ks = 0; ks < 2; ks++) {
            const int kk = ks * 16;
            uint32_t afh[2][4], afl[2][4], bfh[8][2], bfl[8][2];
            #pragma unroll
            for (int t = 0; t < 2; t++) {
                const float* ap = Ab + (wm + t * 16 + r) * LDSA + kk + 2 * c;
                split2(*(const float2*)(ap),                afh[t][0], afl[t][0]);
                split2(*(const float2*)(ap + 8 * LDSA),     afh[t][1], afl[t][1]);
                split2(*(const float2*)(ap + 8),            afh[t][2], afl[t][2]);
                split2(*(const float2*)(ap + 8 * LDSA + 8), afh[t][3], afl[t][3]);
            }
            #pragma unroll
            for (int u = 0; u < 8; u++) {
                const float* bp = Bb + (wn + u * 8 + r) * LDSA + kk + 2 * c;
                split2(*(const float2*)(bp),     bfh[u][0], bfl[u][0]);
                split2(*(const float2*)(bp + 8), bfh[u][1], bfl[u][1]);
            }
            #pragma unroll
            for (int t = 0; t < 2; t++)
                #pragma unroll
                for (int u = 0; u < 8; u++) {
                    mma_bf16(acc[t][u], afl[t], bfh[u]);   // lo*hi
                    mma_bf16(acc[t][u], afh[t], bfl[u]);   // hi*lo
                    mma_bf16(acc[t][u], afh[t], bfh[u]);   // hi*hi
                }
        }
        __syncthreads();
        if (kt + 2 < 8) load_tile(kt + 2, buf);
        asm volatile("cp.async.commit_group;" ::: "memory");
    }

    // ---- epilogue ----
    #pragma unroll
    for (int t = 0; t < 2; t++) {
        const int row0 = bm + wm + t * 16 + r;
        #pragma unroll
        for (int u = 0; u < 8; u++) {
            const int col = bn0 + wn + u * 8 + 2 * c;
            if (row0 < M)
                *(float2*)(C + (size_t)row0 * NC + col) =
                    make_float2(acc[t][u][0], acc[t][u][1]);
            if (row0 + 8 < M)
                *(float2*)(C + (size_t)(row0 + 8) * NC + col) =
                    make_float2(acc[t][u][2], acc[t][u][3]);
        }
    }
}

// ---------------- batched weight transpose ----------------------------------
struct TPars {
    const float* src[10];
    int K[10], N[10], dstOff[10];
};
__global__ void k_transpose_all(TPars p) {
    const int m = blockIdx.y;
    const int K = p.K[m], Ncols = p.N[m];
    const float* src = p.src[m];
    float* dst = g_wts + p.dstOff[m];
    const int tot = K * Ncols;
    for (int i = blockIdx.x * blockDim.x + threadIdx.x; i < tot;
         i += gridDim.x * blockDim.x) {
        int k = i / Ncols, n = i % Ncols;
        dst[n * K + k] = src[i];
    }
}

// ---------------- edge dtype sniff -----------------------------------------
__global__ void k_detect(const int* e32) {
    __shared__ int nz;
    if (threadIdx.x == 0) nz = 0;
    __syncthreads();
    for (int i = threadIdx.x; i < 2048; i += blockDim.x) {
        if (e32[2 * i + 1] != 0) nz = 1;
    }
    __syncthreads();
    if (threadIdx.x == 0) g_fmt64 = (nz == 0) ? 1 : 0;
}

__device__ __forceinline__ int edge_at(const void* e, int idx) {
    if (g_fmt64) return (int)((const long long*)e)[idx];
    return ((const int*)e)[idx];
}

// ---------------- CSR build (batched over 4 relations) ----------------------
struct EPtr4 { const void* e[4]; };

__global__ void k_zero_counts() {
    int i = blockIdx.x * blockDim.x + threadIdx.x;
    if (i < NN) g_counts[blockIdx.y][i] = 0;
}

__global__ void k_count(EPtr4 ep) {
    int i = blockIdx.x * blockDim.x + threadIdx.x;
    if (i >= EE) return;
    int d = edge_at(ep.e[blockIdx.y], EE + i);
    atomicAdd(&g_counts[blockIdx.y][d], 1);
}

__global__ void k_deg() {
    int i = blockIdx.x * blockDim.x + threadIdx.x;
    if (i < NN) {
        int v = blockIdx.y;
        float dg = (float)(g_counts[v][i] + 1);   // +1 self loop
        g_dinv[v][i]   = rsqrtf(dg);
        g_deginv[v][i] = 1.0f / dg;
    }
}

__global__ void k_scan() {
    const int v = blockIdx.x;
    __shared__ int sh[1024];
    __shared__ int carry;
    if (threadIdx.x == 0) { carry = 0; g_rowptr[v][0] = 0; }
    __syncthreads();
    for (int base = 0; base < NN; base += 1024) {
        int i = base + threadIdx.x;
        int val = (i < NN) ? g_counts[v][i] : 0;
        sh[threadIdx.x] = val;
        __syncthreads();
        for (int d = 1; d < 1024; d <<= 1) {
            int t = (threadIdx.x >= d) ? sh[threadIdx.x - d] : 0;
            __syncthreads();
            sh[threadIdx.x] += t;
            __syncthreads();
        }
        if (i < NN) {
            g_rowptr[v][i + 1] = carry + sh[threadIdx.x];
            g_cursor[v][i] = 0;
        }
        __syncthreads();
        if (threadIdx.x == 0) carry += sh[1023];
        __syncthreads();
    }
}

__global__ void k_fill(EPtr4 ep) {
    int i = blockIdx.x * blockDim.x + threadIdx.x;
    if (i >= EE) return;
    const int v = blockIdx.y;
    int s = edge_at(ep.e[v], i);
    int d = edge_at(ep.e[v], EE + i);
    int pos = g_rowptr[v][d] + atomicAdd(&g_cursor[v][d], 1);
    g_col[v][pos]  = s;
    g_coef[v][pos] = g_dinv[v][s] * g_dinv[v][d];
}

// ---------------- GCN aggregation + self loop + bias + LeakyReLU ------------
template <int F>
__global__ void __launch_bounds__(256)
k_agg(const float* __restrict__ xwBase, Ptr4 bias, float* __restrict__ outBase) {
    constexpr int TPR = F / 4;
    constexpr int RPB = 256 / TPR;
    const int view = blockIdx.y;
    const int rid = threadIdx.x / TPR;
    const int f4  = threadIdx.x % TPR;
    const int row = blockIdx.x * RPB + rid;
    if (row >= NN) return;

    const float* __restrict__ xw = xwBase + (size_t)view * NN * F;
    float* __restrict__ out      = outBase + (size_t)view * NN * F;
    const int* __restrict__ rp   = g_rowptr[view];
    const int* __restrict__ col  = g_col[view];
    const float* __restrict__ cf = g_coef[view];

    const int start = rp[row];
    const int end   = rp[row + 1];
    float4 acc = make_float4(0.f, 0.f, 0.f, 0.f);
    for (int p = start; p < end; p++) {
        const int s    = col[p];
        const float w  = cf[p];
        float4 v = *(const float4*)(xw + (size_t)s * F + f4 * 4);
        acc.x += v.x * w; acc.y += v.y * w;
        acc.z += v.z * w; acc.w += v.w * w;
    }
    const float di = g_deginv[view][row];
    float4 sv = *(const float4*)(xw + (size_t)row * F + f4 * 4);
    float4 bv = *(const float4*)(bias.p[view] + f4 * 4);
    float4 o;
    o.x = acc.x + sv.x * di + bv.x;
    o.y = acc.y + sv.y * di + bv.y;
    o.z = acc.z + sv.z * di + bv.z;
    o.w = acc.w + sv.w * di + bv.w;
    o.x = (o.x >= 0.f) ? o.x : 0.2f * o.x;
    o.y = (o.y >= 0.f) ? o.y : 0.2f * o.y;
    o.z = (o.z >= 0.f) ? o.z : 0.2f * o.z;
    o.w = (o.w >= 0.f) ? o.w : 0.2f * o.w;
    *(float4*)(out + (size_t)row * F + f4 * 4) = o;
}

// ---------------- final combine (batched over 2 node types) ----------------
__global__ void k_combine(const float* __restrict__ outSecs,
                          Ptr4 rbias, float* __restrict__ dst) {
    const int j = blockIdx.y;
    const size_t SEC = (size_t)NN * FOUT;
    const float* jv  = outSecs + (2 + j) * SEC;
    const float* bv  = outSecs + (4 + j) * SEC;
    const float* res = g_bufC[j];
    int i = blockIdx.x * blockDim.x + threadIdx.x;
    if (i < NN * FOUT) {
        dst[j * SEC + i] = 0.5f * (jv[i] + bv[i]) + res[i]
                         + rbias.p[j][i & (FOUT - 1)];
    }
}

// ---------------- host orchestration ----------------------------------------
#define GEMM_GRID_X ((NN + 127) / 128)

extern "C" void kernel_launch(void* const* d_in, const int* in_sizes, int n_in,
                              void* d_out, int out_size) {
    const float* x_lj = (const float*)d_in[0];
    const float* x_pj = (const float*)d_in[1];
    const float* x_lb = (const float*)d_in[2];
    const float* x_pb = (const float*)d_in[3];

    EPtr4 ep; ep.e[0] = d_in[4]; ep.e[1] = d_in[5]; ep.e[2] = d_in[6]; ep.e[3] = d_in[7];

    const float* W_j1_l = (const float*)d_in[8];   const float* b_j1_l = (const float*)d_in[9];
    const float* W_j1_p = (const float*)d_in[10];  const float* b_j1_p = (const float*)d_in[11];
    const float* W_j2_l = (const float*)d_in[12];  const float* b_j2_l = (const float*)d_in[13];
    const float* W_j2_p = (const float*)d_in[14];  const float* b_j2_p = (const float*)d_in[15];
    const float* W_b1_l = (const float*)d_in[16];  const float* b_b1_l = (const float*)d_in[17];
    const float* W_b1_p = (const float*)d_in[18];  const float* b_b1_p = (const float*)d_in[19];
    const float* W_b2_l = (const float*)d_in[20];  const float* b_b2_l = (const float*)d_in[21];
    const float* W_b2_p = (const float*)d_in[22];  const float* b_b2_p = (const float*)d_in[23];
    const float* W_r_l  = (const float*)d_in[24];  const float* b_r_l  = (const float*)d_in[25];
    const float* W_r_p  = (const float*)d_in[26];  const float* b_r_p  = (const float*)d_in[27];

    float* out = (float*)d_out;
    const size_t SEC = (size_t)NN * FOUT;

    float *bufA, *bufB, *bufC, *wts;
    cudaGetSymbolAddress((void**)&bufA, g_bufA);
    cudaGetSymbolAddress((void**)&bufB, g_bufB);
    cudaGetSymbolAddress((void**)&bufC, g_bufC);
    cudaGetSymbolAddress((void**)&wts,  g_wts);

    cudaFuncSetAttribute(k_gemm<256>, cudaFuncAttributeMaxDynamicSharedMemorySize, SMEM_GEMM);
    cudaFuncSetAttribute(k_gemm<128>, cudaFuncAttributeMaxDynamicSharedMemorySize, SMEM_GEMM);

    // view order: 0=jl (jac/lnc), 1=jp (jac/prot), 2=bl (blast/lnc), 3=bp (blast/prot)

    // 1) edge dtype
    k_detect<<<1, 256>>>((const int*)ep.e[0]);

    // 2-6) CSR build, batched
    dim3 gz((NN + 255) / 256, 4);
    dim3 ge((EE + 255) / 256, 4);
    k_zero_counts<<<gz, 256>>>();
    k_count<<<ge, 256>>>(ep);
    k_deg<<<gz, 256>>>();
    k_scan<<<4, 1024>>>();
    k_fill<<<ge, 256>>>(ep);

    // 7) all weight transposes
    TPars tp;
    const float* ws[10] = {W_j1_l, W_j1_p, W_b1_l, W_b1_p,
                           W_j2_l, W_j2_p, W_b2_l, W_b2_p, W_r_l, W_r_p};
    for (int m = 0; m < 10; m++) {
        tp.src[m] = ws[m];
        tp.K[m] = 256;
        tp.N[m] = (m < 4) ? 256 : 128;
        tp.dstOff[m] = (m < 4) ? m * 65536 : 4 * 65536 + (m - 4) * 32768;
    }
    k_transpose_all<<<dim3(64, 10), 256>>>(tp);

    // 8) layer-1 GEMMs, all 4 views
    Ptr4 ax; ax.p[0] = x_lj; ax.p[1] = x_pj; ax.p[2] = x_lb; ax.p[3] = x_pb;
    k_gemm<256><<<dim3(GEMM_GRID_X, 2, 4), 256, SMEM_GEMM>>>(
        ax, wts, 65536, bufA, (size_t)NN * HID, NN);

    // 9) agg layer 1
    Ptr4 b1; b1.p[0] = b_j1_l; b1.p[1] = b_j1_p; b1.p[2] = b_b1_l; b1.p[3] = b_b1_p;
    k_agg<HID><<<dim3((NN + 3) / 4, 4), 256>>>(bufA, b1, bufB);

    // 10) layer-2 GEMMs
    Ptr4 a2; a2.p[0] = bufB; a2.p[1] = bufB + (size_t)NN * HID;
    a2.p[2] = bufB + 2 * (size_t)NN * HID; a2.p[3] = bufB + 3 * (size_t)NN * HID;
    k_gemm<128><<<dim3(GEMM_GRID_X, 1, 4), 256, SMEM_GEMM>>>(
        a2, wts + 4 * 65536, 32768, bufC, (size_t)NN * FOUT, NN);

    // 11) agg layer 2 -> output sections 2..5 (jl, jp, bl, bp)
    Ptr4 b2; b2.p[0] = b_j2_l; b2.p[1] = b_j2_p; b2.p[2] = b_b2_l; b2.p[3] = b_b2_p;
    k_agg<FOUT><<<dim3((NN + 7) / 8, 4), 256>>>(bufC, b2, out + 2 * SEC);

    // 12) residual GEMMs (2 views) -> bufC[0], bufC[1]
    Ptr4 ar; ar.p[0] = x_lj; ar.p[1] = x_pj; ar.p[2] = x_lj; ar.p[3] = x_pj;
    k_gemm<128><<<dim3(GEMM_GRID_X, 1, 2), 256, SMEM_GEMM>>>(
        ar, wts + 4 * 65536 + 4 * 32768, 32768, bufC, (size_t)NN * FOUT, NN);

    // 13) combine
    Ptr4 rb; rb.p[0] = b_r_l; rb.p[1] = b_r_p; rb.p[2] = b_r_l; rb.p[3] = b_r_p;
    k_combine<<<dim3((NN * FOUT + 255) / 256, 2), 256>>>(out, rb, out);
}